// round 5
// baseline (speedup 1.0000x reference)
#include <cuda_runtime.h>
#include <cuda_bf16.h>

#define BATCH 256
#define NV 10475
#define NJ 55
#define PB 486            // pose basis = 54*9
#define NC3 (NV*3)        // 31425
#define JOFF (BATCH*NC3)  // offset of joints in d_out

// ---- scratch (device globals; no allocation allowed) ----
__device__ float g_jreg[3465];            // (55, 63): [vt(3) | sh(30) | ex(30)]
__device__ float g_pf[PB * BATCH];        // pose feature, TRANSPOSED [k][b]
__device__ float g_Arel[BATCH * NJ * 12];

__constant__ int c_parents[NJ] = {
    -1, 0, 0, 0, 1, 2, 3, 4, 5, 6, 7, 8, 9, 9, 9, 12, 13, 14, 16, 17, 18, 19,
    15, 15, 15, 20, 25, 26, 20, 28, 29, 20, 31, 32, 20, 34, 35, 20, 37, 38,
    21, 40, 41, 21, 43, 44, 21, 46, 47, 21, 49, 50, 21, 52, 53};

// full_pose joint j -> source rotation matrix pointer for batch b
__device__ __forceinline__ const float* joint_R(
    int j, int b, const float* wr, const float* bp, const float* jaw,
    const float* le, const float* re, const float* lh, const float* rh)
{
    if (j == 0)  return wr + b * 9;
    if (j <= 21) return bp + (b * 21 + (j - 1)) * 9;
    if (j == 22) return jaw + b * 9;
    if (j == 23) return le + b * 9;
    if (j == 24) return re + b * 9;
    if (j <= 39) return lh + (b * 15 + (j - 25)) * 9;
    return rh + (b * 15 + (j - 40)) * 9;
}

// ---- K1: fused JR @ [vt | shapedirs | expr_dirs] -> g_jreg (55,63) ----
__global__ __launch_bounds__(256) void jr_kernel(
    const float* __restrict__ JR, const float* __restrict__ vt,
    const float* __restrict__ sh, const float* __restrict__ ex)
{
    int j = blockIdx.x;
    int tid = threadIdx.x;
    __shared__ float jr_s[256];
    __shared__ float part[256];
    int c = tid % 63;
    int g = tid / 63;
    bool active = tid < 252;
    float acc = 0.f;

    for (int v0 = 0; v0 < NV; v0 += 256) {
        int vload = v0 + tid;
        jr_s[tid] = (vload < NV) ? JR[j * NV + vload] : 0.f;
        __syncthreads();
        if (active) {
            #pragma unroll 4
            for (int vv = g; vv < 256; vv += 4) {
                int gv = v0 + vv;
                if (gv < NV) {
                    float d;
                    if (c < 3)       d = vt[gv * 3 + c];
                    else if (c < 33) d = sh[gv * 30 + (c - 3)];
                    else             d = ex[gv * 30 + (c - 33)];
                    acc += jr_s[vv] * d;
                }
            }
        }
        __syncthreads();
    }
    part[tid] = active ? acc : 0.f;
    __syncthreads();
    if (tid < 63)
        g_jreg[j * 63 + tid] =
            part[tid] + part[63 + tid] + part[126 + tid] + part[189 + tid];
}

// ---- K2: per-batch joints + kinematic chain + A_rel + joints out + pf ----
__global__ __launch_bounds__(64) void chain_kernel(
    const float* __restrict__ wr, const float* __restrict__ bp,
    const float* __restrict__ jaw, const float* __restrict__ le,
    const float* __restrict__ re, const float* __restrict__ lh,
    const float* __restrict__ rh, const float* __restrict__ shape,
    const float* __restrict__ expr, const float* __restrict__ tsl,
    float* __restrict__ out)
{
    int b = blockIdx.x;
    int tid = threadIdx.x;
    __shared__ float R_s[NJ * 9];
    __shared__ float J_s[NJ * 3];
    __shared__ float rel_s[NJ * 3];
    __shared__ float A_s[NJ * 12];

    for (int idx = tid; idx < NJ * 9; idx += 64) {
        int j = idx / 9, e = idx % 9;
        R_s[idx] = joint_R(j, b, wr, bp, jaw, le, re, lh, rh)[e];
    }
    for (int idx = tid; idx < NJ * 3; idx += 64) {
        int j = idx / 3, c = idx % 3;
        const float* base = g_jreg + j * 63;
        float v = base[c];
        #pragma unroll
        for (int k = 0; k < 10; k++) v += base[3 + c * 10 + k] * shape[b * 10 + k];
        #pragma unroll
        for (int k = 0; k < 10; k++) v += base[33 + c * 10 + k] * expr[b * 10 + k];
        J_s[idx] = v;
    }
    __syncthreads();
    for (int idx = tid; idx < NJ * 3; idx += 64) {
        int j = idx / 3, c = idx % 3;
        rel_s[idx] = J_s[idx] - ((j > 0) ? J_s[c_parents[j] * 3 + c] : 0.f);
    }
    __syncthreads();

    if (tid < 12) {
        int r = tid / 4, c = tid % 4;
        A_s[r * 4 + c] = (c < 3) ? R_s[r * 3 + c] : rel_s[r];
        __syncwarp(0x0FFF);
        for (int i = 1; i < NJ; i++) {
            int p = c_parents[i];
            const float* Ap = A_s + p * 12;
            float v;
            if (c < 3)
                v = Ap[r * 4 + 0] * R_s[i * 9 + 0 + c] +
                    Ap[r * 4 + 1] * R_s[i * 9 + 3 + c] +
                    Ap[r * 4 + 2] * R_s[i * 9 + 6 + c];
            else
                v = Ap[r * 4 + 0] * rel_s[i * 3 + 0] +
                    Ap[r * 4 + 1] * rel_s[i * 3 + 1] +
                    Ap[r * 4 + 2] * rel_s[i * 3 + 2] + Ap[r * 4 + 3];
            A_s[i * 12 + r * 4 + c] = v;
            __syncwarp(0x0FFF);
        }
    }
    __syncthreads();

    // joints output: posed + tsl
    for (int idx = tid; idx < NJ * 3; idx += 64) {
        int j = idx / 3, c = idx % 3;
        out[JOFF + b * (NJ * 3) + idx] = A_s[j * 12 + c * 4 + 3] + tsl[b * 3 + c];
    }
    // A_rel with corrected translation
    for (int idx = tid; idx < NJ * 12; idx += 64) {
        int j = idx / 12, e = idx % 12, r = e / 4, c = e % 4;
        float v;
        if (c < 3)
            v = A_s[j * 12 + r * 4 + c];
        else
            v = A_s[j * 12 + r * 4 + 3] -
                (A_s[j * 12 + r * 4 + 0] * J_s[j * 3 + 0] +
                 A_s[j * 12 + r * 4 + 1] * J_s[j * 3 + 1] +
                 A_s[j * 12 + r * 4 + 2] * J_s[j * 3 + 2]);
        g_Arel[b * (NJ * 12) + idx] = v;
    }
    // pose feature, transposed layout [r][b]
    for (int idx = tid; idx < PB; idx += 64) {
        int e = idx % 9;
        float v = R_s[9 + idx] - ((e == 0 || e == 4 || e == 8) ? 1.f : 0.f);
        g_pf[idx * BATCH + b] = v;
    }
}

// ---- K3: fused pose-blend GEMM + shape blend + LBS skinning ----
#define BB 32   // batches per block
#define BV 64   // vertices per block
#define KC 18   // k chunk; 486 = 27*18 exactly (no padding, no guards)
#define NKC 27
#define JG 10   // joints per A_rel staging group
#define PDS 68  // padded vert-plane stride (bank-conflict-free staging)

// smem word map:
//  GEMM phase: pf_s [18][32] @0 (576), pd_s [18][3][68] @576 (3672) -> 4248
//  EPI  phase: sh_s [30][64] @0 (1920), ex_s @1920 (1920), vt_s @3840 (192),
//              w_s @4032 (3520), be_s @7552 (320), exb_s @7872 (320),
//              ts_s @8192 (96) -> 8288
//  ar_s (skinning stage) overlaps @0..3840 (sh/ex dead after vp): 32*10*12=3840
#define SMEM_WORDS 8288

__global__ __launch_bounds__(256, 2) void lbs_kernel(
    const float* __restrict__ posedirs, const float* __restrict__ v_template,
    const float* __restrict__ shapedirs, const float* __restrict__ expr_dirs,
    const float* __restrict__ lbsw, const float* __restrict__ body_shape,
    const float* __restrict__ expr_shape, const float* __restrict__ tsl,
    float* __restrict__ out_verts)
{
    int vt0 = blockIdx.x * BV;
    int b0 = blockIdx.y * BB;
    int tid = threadIdx.x;
    int vloc = tid & 31;
    int v2 = 2 * vloc;        // local vert pair base
    int bg = tid >> 5;        // warp id: batches bg*4..bg*4+3 (warp-uniform)

    __shared__ __align__(16) float smem[SMEM_WORDS];
    float* pf_s = smem;            // [KC][BB]
    float* pd_s = smem + 576;      // [KC][3][PDS]

    float acc[4][2][3];
    #pragma unroll
    for (int i = 0; i < 4; i++)
        #pragma unroll
        for (int s = 0; s < 2; s++)
            #pragma unroll
            for (int c = 0; c < 3; c++) acc[i][s][c] = 0.f;

    int col0 = vt0 * 3;
    for (int kc = 0; kc < NKC; kc++) {
        int k0 = kc * KC;
        for (int idx = tid; idx < KC * BB; idx += 256) {
            int k = idx >> 5, bb = idx & 31;
            pf_s[idx] = g_pf[(k0 + k) * BATCH + b0 + bb];
        }
        for (int idx = tid; idx < KC * 192; idx += 256) {
            int k = idx / 192, col = idx - k * 192;
            int v = col / 3, c = col - v * 3;
            int gc = col0 + col;
            float val = (gc < NC3) ? posedirs[(k0 + k) * NC3 + gc] : 0.f;
            pd_s[k * (3 * PDS) + c * PDS + v] = val;
        }
        __syncthreads();
        #pragma unroll
        for (int k = 0; k < KC; k++) {
            const float4 av = *(const float4*)(pf_s + k * 32 + bg * 4); // bcast
            const float* row = pd_s + k * (3 * PDS) + v2;
            float2 p0 = *(const float2*)(row);
            float2 p1 = *(const float2*)(row + PDS);
            float2 p2 = *(const float2*)(row + 2 * PDS);
            float a[4] = {av.x, av.y, av.z, av.w};
            #pragma unroll
            for (int i = 0; i < 4; i++) {
                acc[i][0][0] += a[i] * p0.x;  acc[i][1][0] += a[i] * p0.y;
                acc[i][0][1] += a[i] * p1.x;  acc[i][1][1] += a[i] * p1.y;
                acc[i][0][2] += a[i] * p2.x;  acc[i][1][2] += a[i] * p2.y;
            }
        }
        __syncthreads();
    }

    // ---- epilogue staging ----
    float* sh_s  = smem;            // [30][64]  (e-major: [c*10+k][v])
    float* ex_s  = smem + 1920;     // [30][64]
    float* vt_s  = smem + 3840;     // [3][64]
    float* w_s   = smem + 4032;     // [55][64]
    float* be_s  = smem + 7552;     // [32][10]
    float* exb_s = smem + 7872;     // [32][10]
    float* ts_s  = smem + 8192;     // [32][3]

    for (int idx = tid; idx < 1920; idx += 256) {
        int e = idx / 64, v = idx & 63;
        int gv = vt0 + v;
        sh_s[idx] = (gv < NV) ? shapedirs[gv * 30 + e] : 0.f;
        ex_s[idx] = (gv < NV) ? expr_dirs[gv * 30 + e] : 0.f;
    }
    for (int idx = tid; idx < 192; idx += 256) {
        int c = idx / 64, v = idx & 63;
        int gv = vt0 + v;
        vt_s[idx] = (gv < NV) ? v_template[gv * 3 + c] : 0.f;
    }
    for (int idx = tid; idx < 3520; idx += 256) {
        int j = idx / 64, v = idx & 63;
        int gv = vt0 + v;
        w_s[idx] = (gv < NV) ? lbsw[gv * 55 + j] : 0.f;
    }
    for (int idx = tid; idx < 320; idx += 256) {
        int bb = idx / 10, k = idx % 10;
        be_s[idx]  = body_shape[(b0 + bb) * 10 + k];
        exb_s[idx] = expr_shape[(b0 + bb) * 10 + k];
    }
    for (int idx = tid; idx < 96; idx += 256)
        ts_s[idx] = tsl[b0 * 3 + idx];
    __syncthreads();

    // v_posed in-place into acc: + v_template + shape blend + expr blend
    #pragma unroll
    for (int c = 0; c < 3; c++) {
        float2 t = *(const float2*)(vt_s + c * 64 + v2);
        #pragma unroll
        for (int i = 0; i < 4; i++) {
            acc[i][0][c] += t.x;
            acc[i][1][c] += t.y;
        }
    }
    #pragma unroll
    for (int k = 0; k < 10; k++) {
        float be[4], exb[4];
        #pragma unroll
        for (int i = 0; i < 4; i++) {
            be[i]  = be_s[(bg * 4 + i) * 10 + k];
            exb[i] = exb_s[(bg * 4 + i) * 10 + k];
        }
        #pragma unroll
        for (int c = 0; c < 3; c++) {
            float2 s2 = *(const float2*)(sh_s + (c * 10 + k) * 64 + v2);
            float2 e2 = *(const float2*)(ex_s + (c * 10 + k) * 64 + v2);
            #pragma unroll
            for (int i = 0; i < 4; i++) {
                acc[i][0][c] += be[i] * s2.x + exb[i] * e2.x;
                acc[i][1][c] += be[i] * s2.y + exb[i] * e2.y;
            }
        }
    }

    float o[4][2][3];
    #pragma unroll
    for (int i = 0; i < 4; i++)
        #pragma unroll
        for (int s = 0; s < 2; s++)
            #pragma unroll
            for (int c = 0; c < 3; c++) o[i][s][c] = 0.f;

    // skinning: A_rel staged in groups of JG joints into dead sh/ex region
    float* ar_s = smem;  // [32][JG*12] = 3840 words
    for (int j0 = 0; j0 < NJ; j0 += JG) {
        int njg = (NJ - j0 < JG) ? (NJ - j0) : JG;
        __syncthreads();
        int total = BB * njg * 12;
        for (int idx = tid; idx < total; idx += 256) {
            int bb = idx / (njg * 12);
            int rem = idx % (njg * 12);
            ar_s[bb * (JG * 12) + rem] =
                g_Arel[(b0 + bb) * (NJ * 12) + j0 * 12 + rem];
        }
        __syncthreads();
        for (int jj = 0; jj < njg; jj++) {
            int j = j0 + jj;
            float2 w = *(const float2*)(w_s + j * 64 + v2);
            #pragma unroll
            for (int i = 0; i < 4; i++) {
                const float* mb = ar_s + (bg * 4 + i) * (JG * 12) + jj * 12;
                float2 m01 = *(const float2*)(mb + 0);
                float2 m23 = *(const float2*)(mb + 2);
                float2 m45 = *(const float2*)(mb + 4);
                float2 m67 = *(const float2*)(mb + 6);
                float2 m89 = *(const float2*)(mb + 8);
                float2 mAB = *(const float2*)(mb + 10);
                #pragma unroll
                for (int s = 0; s < 2; s++) {
                    float ws = (s == 0) ? w.x : w.y;
                    float x = acc[i][s][0], y = acc[i][s][1], z = acc[i][s][2];
                    o[i][s][0] += ws * (m01.x * x + m01.y * y + m23.x * z + m23.y);
                    o[i][s][1] += ws * (m45.x * x + m45.y * y + m67.x * z + m67.y);
                    o[i][s][2] += ws * (m89.x * x + m89.y * y + mAB.x * z + mAB.y);
                }
            }
        }
    }

    // store: SCALAR stores (b*NC3 is odd-word for odd b -> float2 would trap)
    #pragma unroll
    for (int i = 0; i < 4; i++) {
        int bl = bg * 4 + i;
        int b = b0 + bl;
        float t0 = ts_s[bl * 3], t1 = ts_s[bl * 3 + 1], t2 = ts_s[bl * 3 + 2];
        int va = vt0 + v2;
        float* p = out_verts + b * NC3 + va * 3;
        if (va < NV) {
            p[0] = o[i][0][0] + t0;
            p[1] = o[i][0][1] + t1;
            p[2] = o[i][0][2] + t2;
        }
        if (va + 1 < NV) {
            p[3] = o[i][1][0] + t0;
            p[4] = o[i][1][1] + t1;
            p[5] = o[i][1][2] + t2;
        }
    }
}

extern "C" void kernel_launch(void* const* d_in, const int* in_sizes, int n_in,
                              void* d_out, int out_size)
{
    const float* world_rot  = (const float*)d_in[0];
    const float* world_tsl  = (const float*)d_in[1];
    const float* body_shape = (const float*)d_in[2];
    const float* body_pose  = (const float*)d_in[3];
    const float* lhand      = (const float*)d_in[4];
    const float* rhand      = (const float*)d_in[5];
    const float* expr_shape = (const float*)d_in[6];
    const float* jaw        = (const float*)d_in[7];
    const float* leye       = (const float*)d_in[8];
    const float* reye       = (const float*)d_in[9];
    const float* v_template = (const float*)d_in[10];
    const float* shapedirs  = (const float*)d_in[11];
    const float* expr_dirs  = (const float*)d_in[12];
    const float* posedirs   = (const float*)d_in[13];
    const float* J_reg      = (const float*)d_in[14];
    const float* lbsw       = (const float*)d_in[15];
    float* out = (float*)d_out;

    jr_kernel<<<NJ, 256>>>(J_reg, v_template, shapedirs, expr_dirs);
    chain_kernel<<<BATCH, 64>>>(world_rot, body_pose, jaw, leye, reye, lhand,
                                rhand, body_shape, expr_shape, world_tsl, out);
    dim3 grid((NV + BV - 1) / BV, BATCH / BB);
    lbs_kernel<<<grid, 256>>>(posedirs, v_template, shapedirs, expr_dirs,
                              lbsw, body_shape, expr_shape, world_tsl, out);
}

// round 6
// speedup vs baseline: 2.2635x; 2.2635x over previous
#include <cuda_runtime.h>
#include <cuda_bf16.h>

#define BATCH 256
#define NV 10475
#define NJ 55
#define PB 486            // pose basis = 54*9
#define NC3 (NV*3)        // 31425
#define JOFF (BATCH*NC3)  // offset of joints in d_out

// ---- scratch (device globals; no allocation allowed) ----
#define CHUNK 96
#define NCH 110           // ceil(10475/96)
__device__ float g_jr_partial[NCH * 3465];
__device__ float g_jreg[3465];          // (55, 63): [vt(3) | sh(30) | ex(30)]
__device__ float g_pf[BATCH * PB];      // pose feature [b][k]
__device__ float g_Arel[BATCH * NJ * 12];

__constant__ int c_parents[NJ] = {
    -1, 0, 0, 0, 1, 2, 3, 4, 5, 6, 7, 8, 9, 9, 9, 12, 13, 14, 16, 17, 18, 19,
    15, 15, 15, 20, 25, 26, 20, 28, 29, 20, 31, 32, 20, 34, 35, 20, 37, 38,
    21, 40, 41, 21, 43, 44, 21, 46, 47, 21, 49, 50, 21, 52, 53};

// full_pose joint j -> source rotation matrix pointer for batch b
__device__ __forceinline__ const float* joint_R(
    int j, int b, const float* wr, const float* bp, const float* jaw,
    const float* le, const float* re, const float* lh, const float* rh)
{
    if (j == 0)  return wr + b * 9;
    if (j <= 21) return bp + (b * 21 + (j - 1)) * 9;
    if (j == 22) return jaw + b * 9;
    if (j == 23) return le + b * 9;
    if (j == 24) return re + b * 9;
    if (j <= 39) return lh + (b * 15 + (j - 25)) * 9;
    return rh + (b * 15 + (j - 40)) * 9;
}

// ---- K1: partial JR @ [vt | shapedirs | expr_dirs] per vertex chunk ----
__global__ __launch_bounds__(128) void jr_partial_kernel(
    const float* __restrict__ JR, const float* __restrict__ vt,
    const float* __restrict__ sh, const float* __restrict__ ex)
{
    __shared__ float jr_s[NJ * CHUNK];   // 55*96
    __shared__ float d_s[CHUNK * 63];    // 96*63
    int chunk = blockIdx.x;
    int v0 = chunk * CHUNK;
    int tid = threadIdx.x;

    for (int idx = tid; idx < NJ * CHUNK; idx += 128) {
        int j = idx / CHUNK, t = idx % CHUNK;
        int v = v0 + t;
        jr_s[idx] = (v < NV) ? JR[j * NV + v] : 0.f;
    }
    for (int idx = tid; idx < CHUNK * 63; idx += 128) {
        int t = idx / 63, c = idx % 63;
        int v = v0 + t;
        float val = 0.f;
        if (v < NV) {
            if (c < 3)       val = vt[v * 3 + c];
            else if (c < 33) val = sh[v * 30 + (c - 3)];
            else             val = ex[v * 30 + (c - 33)];
        }
        d_s[idx] = val;
    }
    __syncthreads();
    for (int o = tid; o < 3465; o += 128) {
        int j = o / 63, c = o % 63;
        float sum = 0.f;
        #pragma unroll 8
        for (int t = 0; t < CHUNK; t++)
            sum += jr_s[j * CHUNK + t] * d_s[t * 63 + c];
        g_jr_partial[chunk * 3465 + o] = sum;
    }
}

// ---- K2: reduce partials ----
__global__ void jr_reduce_kernel()
{
    int o = blockIdx.x * 256 + threadIdx.x;
    if (o >= 3465) return;
    float s = 0.f;
    for (int ch = 0; ch < NCH; ch++) s += g_jr_partial[ch * 3465 + o];
    g_jreg[o] = s;
}

// ---- K3: pose feature (R - I for joints 1..54) ----
__global__ void pf_kernel(
    const float* __restrict__ bp, const float* __restrict__ jaw,
    const float* __restrict__ le, const float* __restrict__ re,
    const float* __restrict__ lh, const float* __restrict__ rh)
{
    int idx = blockIdx.x * blockDim.x + threadIdx.x;
    if (idx >= BATCH * PB) return;
    int b = idx / PB, r = idx % PB;
    int j = 1 + r / 9, e = r % 9;
    const float* R = joint_R(j, b, nullptr, bp, jaw, le, re, lh, rh);
    float v = R[e] - ((e == 0 || e == 4 || e == 8) ? 1.f : 0.f);
    g_pf[idx] = v;
}

// ---- K4: per-batch joints + kinematic chain + A_rel + joints output ----
__global__ __launch_bounds__(64) void chain_kernel(
    const float* __restrict__ wr, const float* __restrict__ bp,
    const float* __restrict__ jaw, const float* __restrict__ le,
    const float* __restrict__ re, const float* __restrict__ lh,
    const float* __restrict__ rh, const float* __restrict__ shape,
    const float* __restrict__ expr, const float* __restrict__ tsl,
    float* __restrict__ out)
{
    int b = blockIdx.x;
    int tid = threadIdx.x;
    __shared__ float R_s[NJ * 9];
    __shared__ float J_s[NJ * 3];
    __shared__ float rel_s[NJ * 3];
    __shared__ float A_s[NJ * 12];

    for (int idx = tid; idx < NJ * 9; idx += 64) {
        int j = idx / 9, e = idx % 9;
        R_s[idx] = joint_R(j, b, wr, bp, jaw, le, re, lh, rh)[e];
    }
    for (int idx = tid; idx < NJ * 3; idx += 64) {
        int j = idx / 3, c = idx % 3;
        const float* base = g_jreg + j * 63;
        float v = base[c];
        #pragma unroll
        for (int k = 0; k < 10; k++) v += base[3 + c * 10 + k] * shape[b * 10 + k];
        #pragma unroll
        for (int k = 0; k < 10; k++) v += base[33 + c * 10 + k] * expr[b * 10 + k];
        J_s[idx] = v;
    }
    __syncthreads();
    for (int idx = tid; idx < NJ * 3; idx += 64) {
        int j = idx / 3, c = idx % 3;
        rel_s[idx] = J_s[idx] - ((j > 0) ? J_s[c_parents[j] * 3 + c] : 0.f);
    }
    __syncthreads();

    if (tid < 12) {
        int r = tid / 4, c = tid % 4;
        A_s[r * 4 + c] = (c < 3) ? R_s[r * 3 + c] : rel_s[r];
        __syncwarp(0x0FFF);
        for (int i = 1; i < NJ; i++) {
            int p = c_parents[i];
            const float* Ap = A_s + p * 12;
            float v;
            if (c < 3)
                v = Ap[r * 4 + 0] * R_s[i * 9 + 0 + c] +
                    Ap[r * 4 + 1] * R_s[i * 9 + 3 + c] +
                    Ap[r * 4 + 2] * R_s[i * 9 + 6 + c];
            else
                v = Ap[r * 4 + 0] * rel_s[i * 3 + 0] +
                    Ap[r * 4 + 1] * rel_s[i * 3 + 1] +
                    Ap[r * 4 + 2] * rel_s[i * 3 + 2] + Ap[r * 4 + 3];
            A_s[i * 12 + r * 4 + c] = v;
            __syncwarp(0x0FFF);
        }
    }
    __syncthreads();

    // joints output: posed + tsl
    for (int idx = tid; idx < NJ * 3; idx += 64) {
        int j = idx / 3, c = idx % 3;
        out[JOFF + b * (NJ * 3) + idx] = A_s[j * 12 + c * 4 + 3] + tsl[b * 3 + c];
    }
    // A_rel with corrected translation
    for (int idx = tid; idx < NJ * 12; idx += 64) {
        int j = idx / 12, e = idx % 12, r = e / 4, c = e % 4;
        float v;
        if (c < 3)
            v = A_s[j * 12 + r * 4 + c];
        else
            v = A_s[j * 12 + r * 4 + 3] -
                (A_s[j * 12 + r * 4 + 0] * J_s[j * 3 + 0] +
                 A_s[j * 12 + r * 4 + 1] * J_s[j * 3 + 1] +
                 A_s[j * 12 + r * 4 + 2] * J_s[j * 3 + 2]);
        g_Arel[b * (NJ * 12) + idx] = v;
    }
}

// ---- K5: fused pose-blend GEMM + shape blend + LBS skinning ----
#define BB 32   // batches per block
#define BV 64   // vertices per block
#define KC 16   // k chunk (double-buffered)
#define NKC 31  // ceil(486/16)
#define JG 10   // joints per A_rel staging group

__global__ __launch_bounds__(256, 2) void lbs_kernel(
    const float* __restrict__ posedirs, const float* __restrict__ v_template,
    const float* __restrict__ shapedirs, const float* __restrict__ expr_dirs,
    const float* __restrict__ lbsw, const float* __restrict__ body_shape,
    const float* __restrict__ expr_shape, const float* __restrict__ tsl,
    float* __restrict__ out_verts)
{
    int vt0 = blockIdx.x * BV;
    int b0 = blockIdx.y * BB;
    int tid = threadIdx.x;
    int vloc = tid & 31;
    int bg = tid >> 5;   // 0..7, 4 batches each

    __shared__ float smem[8704];
    // GEMM phase: pf double-buffer @0 (2*512), pd double-buffer @1024 (2*3072)
    float* pf_s = smem;            // [2][BB*KC]
    float* pd_s = smem + 1024;     // [2][KC*192]

    float acc[4][2][3];
    #pragma unroll
    for (int i = 0; i < 4; i++)
        #pragma unroll
        for (int s2 = 0; s2 < 2; s2++)
            #pragma unroll
            for (int c = 0; c < 3; c++) acc[i][s2][c] = 0.f;

    int col0 = vt0 * 3;

    // ---- stage chunk 0 into buffer 0 ----
    {
        #pragma unroll
        for (int it = 0; it < 2; it++) {
            int idx = it * 256 + tid;            // idx = bb*16 + k
            int bb = idx >> 4, k = idx & 15;
            pf_s[idx] = (k < PB) ? g_pf[(b0 + bb) * PB + k] : 0.f;
        }
        #pragma unroll
        for (int it = 0; it < 12; it++) {
            int idx = it * 256 + tid;
            int k = idx / 192, col = idx - k * 192;
            int gc = col0 + col;
            float v = 0.f;
            if (gc < NC3) v = posedirs[k * NC3 + gc];   // k0=0, k<16<PB
            pd_s[idx] = v;
        }
    }
    __syncthreads();

    int cur = 0;
    for (int kc = 0; kc < NKC; kc++) {
        // ---- prefetch next chunk into registers (overlaps with compute) ----
        float r_pf[2], r_pd[12];
        bool have_next = (kc + 1 < NKC);
        if (have_next) {
            int k0n = (kc + 1) * KC;
            #pragma unroll
            for (int it = 0; it < 2; it++) {
                int idx = it * 256 + tid;
                int bb = idx >> 4, k = idx & 15;
                r_pf[it] = (k0n + k < PB) ? g_pf[(b0 + bb) * PB + k0n + k] : 0.f;
            }
            #pragma unroll
            for (int it = 0; it < 12; it++) {
                int idx = it * 256 + tid;
                int k = idx / 192, col = idx - k * 192;
                int gc = col0 + col;
                float v = 0.f;
                if (k0n + k < PB && gc < NC3) v = posedirs[(k0n + k) * NC3 + gc];
                r_pd[it] = v;
            }
        }

        // ---- compute current chunk ----
        const float* pfb = pf_s + cur * 512;
        const float* pdb = pd_s + cur * 3072;
        #pragma unroll
        for (int k = 0; k < KC; k++) {
            float a[4], p[2][3];
            #pragma unroll
            for (int i = 0; i < 4; i++) a[i] = pfb[(bg * 4 + i) * KC + k];
            #pragma unroll
            for (int s2 = 0; s2 < 2; s2++)
                #pragma unroll
                for (int c = 0; c < 3; c++)
                    p[s2][c] = pdb[k * 192 + (vloc + 32 * s2) * 3 + c];
            #pragma unroll
            for (int i = 0; i < 4; i++)
                #pragma unroll
                for (int s2 = 0; s2 < 2; s2++)
                    #pragma unroll
                    for (int c = 0; c < 3; c++)
                        acc[i][s2][c] += a[i] * p[s2][c];
        }

        // ---- store prefetched data into the other buffer ----
        if (have_next) {
            float* pfn = pf_s + (1 - cur) * 512;
            float* pdn = pd_s + (1 - cur) * 3072;
            #pragma unroll
            for (int it = 0; it < 2; it++)
                pfn[it * 256 + tid] = r_pf[it];
            #pragma unroll
            for (int it = 0; it < 12; it++)
                pdn[it * 256 + tid] = r_pd[it];
        }
        __syncthreads();
        cur ^= 1;
    }

    // ---- epilogue: re-stage smem (identical to the 591us baseline) ----
    float* sh_s  = smem;           // [64][30] 1920   (dead after vp computed)
    float* ex_s  = smem + 1920;    // 1920            (dead after vp computed)
    float* vt_s  = smem + 3840;    // [64][3]  192    (dead after vp computed)
    float* w_s   = smem + 4032;    // [64][55] 3520   (live through j-loop)
    float* be_s  = smem + 7552;    // [32][10] 320    (dead after vp)
    float* exb_s = smem + 7872;    // 320             (dead after vp)
    float* ts_s  = smem + 8192;    // [32][3]  96     (live to the end)

    for (int idx = tid; idx < 1920; idx += 256) {
        int v = idx / 30, e = idx % 30;
        int gv = vt0 + v;
        sh_s[idx] = (gv < NV) ? shapedirs[gv * 30 + e] : 0.f;
        ex_s[idx] = (gv < NV) ? expr_dirs[gv * 30 + e] : 0.f;
    }
    for (int idx = tid; idx < 192; idx += 256) {
        int v = idx / 3, c = idx % 3;
        int gv = vt0 + v;
        vt_s[idx] = (gv < NV) ? v_template[gv * 3 + c] : 0.f;
    }
    for (int idx = tid; idx < 3520; idx += 256) {
        int v = idx / 55, j = idx % 55;
        int gv = vt0 + v;
        w_s[idx] = (gv < NV) ? lbsw[gv * 55 + j] : 0.f;
    }
    for (int idx = tid; idx < 320; idx += 256) {
        int bb = idx / 10, k = idx % 10;
        be_s[idx]  = body_shape[(b0 + bb) * 10 + k];
        exb_s[idx] = expr_shape[(b0 + bb) * 10 + k];
    }
    for (int idx = tid; idx < 96; idx += 256)
        ts_s[idx] = tsl[b0 * 3 + idx];
    __syncthreads();

    // v_posed = pose-correction + v_template + shape blend + expr blend
    float vp[4][2][3];
    #pragma unroll
    for (int i = 0; i < 4; i++) {
        int bl = bg * 4 + i;
        #pragma unroll
        for (int s2 = 0; s2 < 2; s2++) {
            int vl = vloc + 32 * s2;
            #pragma unroll
            for (int c = 0; c < 3; c++) {
                float v = acc[i][s2][c] + vt_s[vl * 3 + c];
                #pragma unroll
                for (int k = 0; k < 10; k++)
                    v += sh_s[vl * 30 + c * 10 + k] * be_s[bl * 10 + k];
                #pragma unroll
                for (int k = 0; k < 10; k++)
                    v += ex_s[vl * 30 + c * 10 + k] * exb_s[bl * 10 + k];
                vp[i][s2][c] = v;
            }
        }
    }

    float o[4][2][3];
    #pragma unroll
    for (int i = 0; i < 4; i++)
        #pragma unroll
        for (int s2 = 0; s2 < 2; s2++)
            #pragma unroll
            for (int c = 0; c < 3; c++) o[i][s2][c] = 0.f;

    // Skinning: stage A_rel in groups of JG joints into the (now dead)
    // sh_s region. [32 batches][JG joints][12] = 3840 floats max.
    float* arg_s = smem;  // overlaps sh_s/ex_s/vt_s — dead after vp
    for (int j0 = 0; j0 < NJ; j0 += JG) {
        int njg = (NJ - j0 < JG) ? (NJ - j0) : JG;
        __syncthreads();   // protect prior reads of arg_s region (incl. vp stage)
        for (int idx = tid; idx < BB * njg * 12; idx += 256) {
            int bb = idx / (njg * 12);
            int rem = idx % (njg * 12);
            arg_s[bb * (JG * 12) + rem] =
                g_Arel[(b0 + bb) * (NJ * 12) + (j0 * 12) + rem];
        }
        __syncthreads();
        for (int jj = 0; jj < njg; jj++) {
            int j = j0 + jj;
            #pragma unroll
            for (int i = 0; i < 4; i++) {
                int bl = bg * 4 + i;
                float m[12];
                #pragma unroll
                for (int e = 0; e < 12; e++)
                    m[e] = arg_s[bl * (JG * 12) + jj * 12 + e];
                #pragma unroll
                for (int s2 = 0; s2 < 2; s2++) {
                    float w = w_s[(vloc + 32 * s2) * 55 + j];
                    float x = vp[i][s2][0], y = vp[i][s2][1], z = vp[i][s2][2];
                    o[i][s2][0] += w * (m[0] * x + m[1] * y + m[2]  * z + m[3]);
                    o[i][s2][1] += w * (m[4] * x + m[5] * y + m[6]  * z + m[7]);
                    o[i][s2][2] += w * (m[8] * x + m[9] * y + m[10] * z + m[11]);
                }
            }
        }
    }

    #pragma unroll
    for (int i = 0; i < 4; i++) {
        int bl = bg * 4 + i;
        int b = b0 + bl;
        #pragma unroll
        for (int s2 = 0; s2 < 2; s2++) {
            int v = vt0 + vloc + 32 * s2;
            if (v < NV) {
                #pragma unroll
                for (int c = 0; c < 3; c++)
                    out_verts[b * NC3 + v * 3 + c] = o[i][s2][c] + ts_s[bl * 3 + c];
            }
        }
    }
}

extern "C" void kernel_launch(void* const* d_in, const int* in_sizes, int n_in,
                              void* d_out, int out_size)
{
    const float* world_rot  = (const float*)d_in[0];
    const float* world_tsl  = (const float*)d_in[1];
    const float* body_shape = (const float*)d_in[2];
    const float* body_pose  = (const float*)d_in[3];
    const float* lhand      = (const float*)d_in[4];
    const float* rhand      = (const float*)d_in[5];
    const float* expr_shape = (const float*)d_in[6];
    const float* jaw        = (const float*)d_in[7];
    const float* leye       = (const float*)d_in[8];
    const float* reye       = (const float*)d_in[9];
    const float* v_template = (const float*)d_in[10];
    const float* shapedirs  = (const float*)d_in[11];
    const float* expr_dirs  = (const float*)d_in[12];
    const float* posedirs   = (const float*)d_in[13];
    const float* J_reg      = (const float*)d_in[14];
    const float* lbsw       = (const float*)d_in[15];
    float* out = (float*)d_out;

    jr_partial_kernel<<<NCH, 128>>>(J_reg, v_template, shapedirs, expr_dirs);
    jr_reduce_kernel<<<(3465 + 255) / 256, 256>>>();
    pf_kernel<<<(BATCH * PB + 255) / 256, 256>>>(body_pose, jaw, leye, reye, lhand, rhand);
    chain_kernel<<<BATCH, 64>>>(world_rot, body_pose, jaw, leye, reye, lhand,
                                rhand, body_shape, expr_shape, world_tsl, out);
    dim3 grid((NV + BV - 1) / BV, BATCH / BB);
    lbs_kernel<<<grid, 256>>>(posedirs, v_template, shapedirs, expr_dirs,
                              lbsw, body_shape, expr_shape, world_tsl, out);
}

// round 7
// speedup vs baseline: 2.4127x; 1.0659x over previous
#include <cuda_runtime.h>
#include <cuda_bf16.h>

#define BATCH 256
#define NV 10475
#define NJ 55
#define PB 486            // pose basis = 54*9
#define NC3 (NV*3)        // 31425
#define JOFF (BATCH*NC3)  // offset of joints in d_out

// ---- scratch (device globals; no allocation allowed) ----
#define CHUNK 96
#define NCH 110           // ceil(10475/96)
__device__ float g_jr_partial[NCH * 3465];
__device__ float g_jreg[3465];          // (55, 63): [vt(3) | sh(30) | ex(30)]
__device__ float g_pf[BATCH * PB];      // pose feature [b][k]
__device__ float g_Arel[BATCH * NJ * 12];

__constant__ int c_parents[NJ] = {
    -1, 0, 0, 0, 1, 2, 3, 4, 5, 6, 7, 8, 9, 9, 9, 12, 13, 14, 16, 17, 18, 19,
    15, 15, 15, 20, 25, 26, 20, 28, 29, 20, 31, 32, 20, 34, 35, 20, 37, 38,
    21, 40, 41, 21, 43, 44, 21, 46, 47, 21, 49, 50, 21, 52, 53};

// full_pose joint j -> source rotation matrix pointer for batch b
__device__ __forceinline__ const float* joint_R(
    int j, int b, const float* wr, const float* bp, const float* jaw,
    const float* le, const float* re, const float* lh, const float* rh)
{
    if (j == 0)  return wr + b * 9;
    if (j <= 21) return bp + (b * 21 + (j - 1)) * 9;
    if (j == 22) return jaw + b * 9;
    if (j == 23) return le + b * 9;
    if (j == 24) return re + b * 9;
    if (j <= 39) return lh + (b * 15 + (j - 25)) * 9;
    return rh + (b * 15 + (j - 40)) * 9;
}

// ---- K1: partial JR @ [vt | shapedirs | expr_dirs] per vertex chunk ----
__global__ __launch_bounds__(128) void jr_partial_kernel(
    const float* __restrict__ JR, const float* __restrict__ vt,
    const float* __restrict__ sh, const float* __restrict__ ex)
{
    __shared__ float jr_s[NJ * CHUNK];   // 55*96
    __shared__ float d_s[CHUNK * 63];    // 96*63
    int chunk = blockIdx.x;
    int v0 = chunk * CHUNK;
    int tid = threadIdx.x;

    for (int idx = tid; idx < NJ * CHUNK; idx += 128) {
        int j = idx / CHUNK, t = idx % CHUNK;
        int v = v0 + t;
        jr_s[idx] = (v < NV) ? JR[j * NV + v] : 0.f;
    }
    for (int idx = tid; idx < CHUNK * 63; idx += 128) {
        int t = idx / 63, c = idx % 63;
        int v = v0 + t;
        float val = 0.f;
        if (v < NV) {
            if (c < 3)       val = vt[v * 3 + c];
            else if (c < 33) val = sh[v * 30 + (c - 3)];
            else             val = ex[v * 30 + (c - 33)];
        }
        d_s[idx] = val;
    }
    __syncthreads();
    for (int o = tid; o < 3465; o += 128) {
        int j = o / 63, c = o % 63;
        float sum = 0.f;
        #pragma unroll 8
        for (int t = 0; t < CHUNK; t++)
            sum += jr_s[j * CHUNK + t] * d_s[t * 63 + c];
        g_jr_partial[chunk * 3465 + o] = sum;
    }
}

// ---- K2: reduce partials ----
__global__ void jr_reduce_kernel()
{
    int o = blockIdx.x * 256 + threadIdx.x;
    if (o >= 3465) return;
    float s = 0.f;
    for (int ch = 0; ch < NCH; ch++) s += g_jr_partial[ch * 3465 + o];
    g_jreg[o] = s;
}

// ---- K3: pose feature (R - I for joints 1..54) ----
__global__ void pf_kernel(
    const float* __restrict__ bp, const float* __restrict__ jaw,
    const float* __restrict__ le, const float* __restrict__ re,
    const float* __restrict__ lh, const float* __restrict__ rh)
{
    int idx = blockIdx.x * blockDim.x + threadIdx.x;
    if (idx >= BATCH * PB) return;
    int b = idx / PB, r = idx % PB;
    int j = 1 + r / 9, e = r % 9;
    const float* R = joint_R(j, b, nullptr, bp, jaw, le, re, lh, rh);
    float v = R[e] - ((e == 0 || e == 4 || e == 8) ? 1.f : 0.f);
    g_pf[idx] = v;
}

// ---- K4: per-batch joints + kinematic chain + A_rel + joints output ----
__global__ __launch_bounds__(64) void chain_kernel(
    const float* __restrict__ wr, const float* __restrict__ bp,
    const float* __restrict__ jaw, const float* __restrict__ le,
    const float* __restrict__ re, const float* __restrict__ lh,
    const float* __restrict__ rh, const float* __restrict__ shape,
    const float* __restrict__ expr, const float* __restrict__ tsl,
    float* __restrict__ out)
{
    int b = blockIdx.x;
    int tid = threadIdx.x;
    __shared__ float R_s[NJ * 9];
    __shared__ float J_s[NJ * 3];
    __shared__ float rel_s[NJ * 3];
    __shared__ float A_s[NJ * 12];

    for (int idx = tid; idx < NJ * 9; idx += 64) {
        int j = idx / 9, e = idx % 9;
        R_s[idx] = joint_R(j, b, wr, bp, jaw, le, re, lh, rh)[e];
    }
    for (int idx = tid; idx < NJ * 3; idx += 64) {
        int j = idx / 3, c = idx % 3;
        const float* base = g_jreg + j * 63;
        float v = base[c];
        #pragma unroll
        for (int k = 0; k < 10; k++) v += base[3 + c * 10 + k] * shape[b * 10 + k];
        #pragma unroll
        for (int k = 0; k < 10; k++) v += base[33 + c * 10 + k] * expr[b * 10 + k];
        J_s[idx] = v;
    }
    __syncthreads();
    for (int idx = tid; idx < NJ * 3; idx += 64) {
        int j = idx / 3, c = idx % 3;
        rel_s[idx] = J_s[idx] - ((j > 0) ? J_s[c_parents[j] * 3 + c] : 0.f);
    }
    __syncthreads();

    if (tid < 12) {
        int r = tid / 4, c = tid % 4;
        A_s[r * 4 + c] = (c < 3) ? R_s[r * 3 + c] : rel_s[r];
        __syncwarp(0x0FFF);
        for (int i = 1; i < NJ; i++) {
            int p = c_parents[i];
            const float* Ap = A_s + p * 12;
            float v;
            if (c < 3)
                v = Ap[r * 4 + 0] * R_s[i * 9 + 0 + c] +
                    Ap[r * 4 + 1] * R_s[i * 9 + 3 + c] +
                    Ap[r * 4 + 2] * R_s[i * 9 + 6 + c];
            else
                v = Ap[r * 4 + 0] * rel_s[i * 3 + 0] +
                    Ap[r * 4 + 1] * rel_s[i * 3 + 1] +
                    Ap[r * 4 + 2] * rel_s[i * 3 + 2] + Ap[r * 4 + 3];
            A_s[i * 12 + r * 4 + c] = v;
            __syncwarp(0x0FFF);
        }
    }
    __syncthreads();

    // joints output: posed + tsl
    for (int idx = tid; idx < NJ * 3; idx += 64) {
        int j = idx / 3, c = idx % 3;
        out[JOFF + b * (NJ * 3) + idx] = A_s[j * 12 + c * 4 + 3] + tsl[b * 3 + c];
    }
    // A_rel with corrected translation
    for (int idx = tid; idx < NJ * 12; idx += 64) {
        int j = idx / 12, e = idx % 12, r = e / 4, c = e % 4;
        float v;
        if (c < 3)
            v = A_s[j * 12 + r * 4 + c];
        else
            v = A_s[j * 12 + r * 4 + 3] -
                (A_s[j * 12 + r * 4 + 0] * J_s[j * 3 + 0] +
                 A_s[j * 12 + r * 4 + 1] * J_s[j * 3 + 1] +
                 A_s[j * 12 + r * 4 + 2] * J_s[j * 3 + 2]);
        g_Arel[b * (NJ * 12) + idx] = v;
    }
}

// ---- K5: tf32 MMA pose-blend GEMM + shape blend + LBS skinning ----
#define BB 32   // batches per block (GEMM M)
#define BV 64   // vertices per block (GEMM N = 192 cols)
#define KC 32   // k chunk (4 mma k-steps)
#define NKC 16  // 512 total k (zero-padded past 486)
#define JG 10   // joints per A_rel staging group

#define PFS 33   // pf_s row stride
#define PDS 200  // pd_s row stride (conflict-free B-frag loads)
#define CS 193   // c_s row stride

// smem word map (max 10944 words = 43.8KB):
//  GEMM : pf_s [32][33] @0 (1056), pd_s [32][200] @1056 (6400) -> 7456
//  EPI-1: c_s [32][193] @0 (6176), sh_s @6176 (1920), ex_s @8096 (1920),
//         vt_s @10016 (192), be_s @10208 (320), exb_s @10528 (320),
//         ts_s @10848 (96) -> 10944
//  EPI-2 (after vp): w_s @0 (3520), arg_s @3520 (3840)  [c_s/sh/ex dead]
#define SMEM_WORDS 10944

__device__ __forceinline__ void mma_tf32(
    float* d, const unsigned* a, const unsigned* b)
{
    asm volatile(
        "mma.sync.aligned.m16n8k8.row.col.f32.tf32.tf32.f32 "
        "{%0,%1,%2,%3}, {%4,%5,%6,%7}, {%8,%9}, {%0,%1,%2,%3};"
        : "+f"(d[0]), "+f"(d[1]), "+f"(d[2]), "+f"(d[3])
        : "r"(a[0]), "r"(a[1]), "r"(a[2]), "r"(a[3]), "r"(b[0]), "r"(b[1]));
}

__global__ __launch_bounds__(256, 2) void lbs_kernel(
    const float* __restrict__ posedirs, const float* __restrict__ v_template,
    const float* __restrict__ shapedirs, const float* __restrict__ expr_dirs,
    const float* __restrict__ lbsw, const float* __restrict__ body_shape,
    const float* __restrict__ expr_shape, const float* __restrict__ tsl,
    float* __restrict__ out_verts)
{
    int vt0 = blockIdx.x * BV;
    int b0 = blockIdx.y * BB;
    int tid = threadIdx.x;
    int lane = tid & 31;
    int warp = tid >> 5;        // 0..7
    int gid = lane >> 2;        // 0..7
    int tig = lane & 3;         // 0..3
    int wr = warp & 1;          // row group (16 batches each)
    int wc = warp >> 1;         // col group (48 cols each)
    int ncol0 = wc * 48;

    __shared__ __align__(16) float smem[SMEM_WORDS];
    float* pf_s = smem;            // [32][PFS]
    float* pd_s = smem + 1056;     // [32][PDS]
    unsigned* pf_u = (unsigned*)pf_s;
    unsigned* pd_u = (unsigned*)pd_s;

    float d[6][4];
    #pragma unroll
    for (int t = 0; t < 6; t++)
        #pragma unroll
        for (int e = 0; e < 4; e++) d[t][e] = 0.f;

    int col0 = vt0 * 3;
    int arow0 = wr * 16 + gid;

    for (int kc = 0; kc < NKC; kc++) {
        int k0 = kc * KC;
        // stage pf [32 bb][32 k], zero-padded past PB
        #pragma unroll
        for (int it = 0; it < 4; it++) {
            int idx = it * 256 + tid;
            int bb = idx >> 5, k = idx & 31;
            float v = 0.f;
            if (k0 + k < PB) v = g_pf[(b0 + bb) * PB + k0 + k];
            pf_s[bb * PFS + k] = v;
        }
        // stage pd [32 k][192 col], zero-padded
        #pragma unroll
        for (int it = 0; it < 24; it++) {
            int idx = it * 256 + tid;
            int k = idx / 192, col = idx - k * 192;
            int gc = col0 + col;
            float v = 0.f;
            if (k0 + k < PB && gc < NC3) v = posedirs[(k0 + k) * NC3 + gc];
            pd_s[k * PDS + col] = v;
        }
        __syncthreads();
        #pragma unroll
        for (int ks = 0; ks < 4; ks++) {
            int kk = ks * 8;
            unsigned a[4];
            a[0] = pf_u[arow0 * PFS + kk + tig];
            a[1] = pf_u[(arow0 + 8) * PFS + kk + tig];
            a[2] = pf_u[arow0 * PFS + kk + tig + 4];
            a[3] = pf_u[(arow0 + 8) * PFS + kk + tig + 4];
            #pragma unroll
            for (int t = 0; t < 6; t++) {
                unsigned b[2];
                int bc = ncol0 + t * 8 + gid;
                b[0] = pd_u[(kk + tig) * PDS + bc];
                b[1] = pd_u[(kk + tig + 4) * PDS + bc];
                mma_tf32(d[t], a, b);
            }
        }
        __syncthreads();
    }

    // ---- EPI-1: store C frags to smem; stage blend data ----
    float* c_s   = smem;            // [32][CS]
    float* sh_s  = smem + 6176;     // [64][30]
    float* ex_s  = smem + 8096;     // [64][30]
    float* vt_s  = smem + 10016;    // [64][3]
    float* be_s  = smem + 10208;    // [32][10]
    float* exb_s = smem + 10528;    // [32][10]
    float* ts_s  = smem + 10848;    // [32][3]

    #pragma unroll
    for (int t = 0; t < 6; t++) {
        int col = ncol0 + t * 8 + 2 * tig;
        c_s[arow0 * CS + col]           = d[t][0];
        c_s[arow0 * CS + col + 1]       = d[t][1];
        c_s[(arow0 + 8) * CS + col]     = d[t][2];
        c_s[(arow0 + 8) * CS + col + 1] = d[t][3];
    }
    for (int idx = tid; idx < 1920; idx += 256) {
        int v = idx / 30, e = idx % 30;
        int gv = vt0 + v;
        sh_s[idx] = (gv < NV) ? shapedirs[gv * 30 + e] : 0.f;
        ex_s[idx] = (gv < NV) ? expr_dirs[gv * 30 + e] : 0.f;
    }
    for (int idx = tid; idx < 192; idx += 256) {
        int v = idx / 3, c = idx % 3;
        int gv = vt0 + v;
        vt_s[idx] = (gv < NV) ? v_template[gv * 3 + c] : 0.f;
    }
    for (int idx = tid; idx < 320; idx += 256) {
        int bb = idx / 10, k = idx % 10;
        be_s[idx]  = body_shape[(b0 + bb) * 10 + k];
        exb_s[idx] = expr_shape[(b0 + bb) * 10 + k];
    }
    for (int idx = tid; idx < 96; idx += 256)
        ts_s[idx] = tsl[b0 * 3 + idx];
    __syncthreads();

    // thread mapping for epilogue (same as R2): warp bg owns 4 batches,
    // lane vloc owns verts vloc and vloc+32
    int vloc = lane;
    int bg = warp;

    // v_posed = pose-correction (c_s) + v_template + shape + expr blends
    float vp[4][2][3];
    #pragma unroll
    for (int i = 0; i < 4; i++) {
        int bl = bg * 4 + i;
        #pragma unroll
        for (int s2 = 0; s2 < 2; s2++) {
            int vl = vloc + 32 * s2;
            #pragma unroll
            for (int c = 0; c < 3; c++) {
                float v = c_s[bl * CS + vl * 3 + c] + vt_s[vl * 3 + c];
                #pragma unroll
                for (int k = 0; k < 10; k++)
                    v += sh_s[vl * 30 + c * 10 + k] * be_s[bl * 10 + k];
                #pragma unroll
                for (int k = 0; k < 10; k++)
                    v += ex_s[vl * 30 + c * 10 + k] * exb_s[bl * 10 + k];
                vp[i][s2][c] = v;
            }
        }
    }

    float o[4][2][3];
    #pragma unroll
    for (int i = 0; i < 4; i++)
        #pragma unroll
        for (int s2 = 0; s2 < 2; s2++)
            #pragma unroll
            for (int c = 0; c < 3; c++) o[i][s2][c] = 0.f;

    // ---- EPI-2: skinning (c_s/sh/ex now dead) ----
    float* w_s   = smem;            // [64][55]
    float* arg_s = smem + 3520;     // [32][JG*12]

    __syncthreads();   // all vp reads done before overwriting region
    for (int idx = tid; idx < 3520; idx += 256) {
        int v = idx / 55, j = idx % 55;
        int gv = vt0 + v;
        w_s[idx] = (gv < NV) ? lbsw[gv * 55 + j] : 0.f;
    }

    for (int j0 = 0; j0 < NJ; j0 += JG) {
        int njg = (NJ - j0 < JG) ? (NJ - j0) : JG;
        __syncthreads();
        for (int idx = tid; idx < BB * njg * 12; idx += 256) {
            int bb = idx / (njg * 12);
            int rem = idx % (njg * 12);
            arg_s[bb * (JG * 12) + rem] =
                g_Arel[(b0 + bb) * (NJ * 12) + (j0 * 12) + rem];
        }
        __syncthreads();
        for (int jj = 0; jj < njg; jj++) {
            int j = j0 + jj;
            #pragma unroll
            for (int i = 0; i < 4; i++) {
                int bl = bg * 4 + i;
                float m[12];
                #pragma unroll
                for (int e = 0; e < 12; e++)
                    m[e] = arg_s[bl * (JG * 12) + jj * 12 + e];
                #pragma unroll
                for (int s2 = 0; s2 < 2; s2++) {
                    float w = w_s[(vloc + 32 * s2) * 55 + j];
                    float x = vp[i][s2][0], y = vp[i][s2][1], z = vp[i][s2][2];
                    o[i][s2][0] += w * (m[0] * x + m[1] * y + m[2]  * z + m[3]);
                    o[i][s2][1] += w * (m[4] * x + m[5] * y + m[6]  * z + m[7]);
                    o[i][s2][2] += w * (m[8] * x + m[9] * y + m[10] * z + m[11]);
                }
            }
        }
    }

    #pragma unroll
    for (int i = 0; i < 4; i++) {
        int bl = bg * 4 + i;
        int b = b0 + bl;
        #pragma unroll
        for (int s2 = 0; s2 < 2; s2++) {
            int v = vt0 + vloc + 32 * s2;
            if (v < NV) {
                #pragma unroll
                for (int c = 0; c < 3; c++)
                    out_verts[b * NC3 + v * 3 + c] = o[i][s2][c] + ts_s[bl * 3 + c];
            }
        }
    }
}

extern "C" void kernel_launch(void* const* d_in, const int* in_sizes, int n_in,
                              void* d_out, int out_size)
{
    const float* world_rot  = (const float*)d_in[0];
    const float* world_tsl  = (const float*)d_in[1];
    const float* body_shape = (const float*)d_in[2];
    const float* body_pose  = (const float*)d_in[3];
    const float* lhand      = (const float*)d_in[4];
    const float* rhand      = (const float*)d_in[5];
    const float* expr_shape = (const float*)d_in[6];
    const float* jaw        = (const float*)d_in[7];
    const float* leye       = (const float*)d_in[8];
    const float* reye       = (const float*)d_in[9];
    const float* v_template = (const float*)d_in[10];
    const float* shapedirs  = (const float*)d_in[11];
    const float* expr_dirs  = (const float*)d_in[12];
    const float* posedirs   = (const float*)d_in[13];
    const float* J_reg      = (const float*)d_in[14];
    const float* lbsw       = (const float*)d_in[15];
    float* out = (float*)d_out;

    jr_partial_kernel<<<NCH, 128>>>(J_reg, v_template, shapedirs, expr_dirs);
    jr_reduce_kernel<<<(3465 + 255) / 256, 256>>>();
    pf_kernel<<<(BATCH * PB + 255) / 256, 256>>>(body_pose, jaw, leye, reye, lhand, rhand);
    chain_kernel<<<BATCH, 64>>>(world_rot, body_pose, jaw, leye, reye, lhand,
                                rhand, body_shape, expr_shape, world_tsl, out);
    dim3 grid((NV + BV - 1) / BV, BATCH / BB);
    lbs_kernel<<<grid, 256>>>(posedirs, v_template, shapedirs, expr_dirs,
                              lbsw, body_shape, expr_shape, world_tsl, out);
}